// round 15
// baseline (speedup 1.0000x reference)
#include <cuda_runtime.h>
#include <cuda_bf16.h>
#include <math.h>
#include <stdint.h>

#define NB 8
#define NT 2048
#define NC 512
#define NK 512
#define SCALE 0.044194173824159216f  // 1/sqrt(512)

// Scratch (device globals: allocation-free per harness rules)
static __device__ __nv_bfloat16 g_xb[(size_t)NB * NT * NC];
static __device__ __nv_bfloat16 g_wb[3 * 512 * 512];
static __device__ __nv_bfloat16 g_qb[(size_t)NB * NT * NK];
static __device__ __nv_bfloat16 g_kb[(size_t)NB * NT * NK];
static __device__ __nv_bfloat16 g_vT[(size_t)NB * NK * NT];  // [b*512+n][s], scaled by 1/Z
static __device__ __nv_bfloat16 g_SP[(size_t)NB * NT * NT];  // bf16 E=exp(S) (masked on diag tiles)
static __device__ float         g_Z [(size_t)NB * NT];       // column sums of exp
static __device__ int           g_unit;                      // attnv work-queue counter

// ---------------------------------------------------------------------------
// helpers
// ---------------------------------------------------------------------------
__device__ __forceinline__ void cpa16(void* dst_smem, const void* src) {
    unsigned s = (unsigned)__cvta_generic_to_shared(dst_smem);
    asm volatile("cp.async.cg.shared.global [%0], [%1], 16;\n" :: "r"(s), "l"(src));
}
#define CP_COMMIT() asm volatile("cp.async.commit_group;\n" ::: "memory")
#define CP_WAIT0()  asm volatile("cp.async.wait_group 0;\n" ::: "memory")
#define CP_WAIT1()  asm volatile("cp.async.wait_group 1;\n" ::: "memory")

#define MMA_BF16(c, a, b0, b1)                                              \
    asm volatile(                                                           \
        "mma.sync.aligned.m16n8k16.row.col.f32.bf16.bf16.f32 "              \
        "{%0,%1,%2,%3},{%4,%5,%6,%7},{%8,%9},{%0,%1,%2,%3};\n"              \
        : "+f"((c)[0]), "+f"((c)[1]), "+f"((c)[2]), "+f"((c)[3])            \
        : "r"((a)[0]), "r"((a)[1]), "r"((a)[2]), "r"((a)[3]),               \
          "r"(b0), "r"(b1))

#define LDSM4(r, a)                                                         \
    asm volatile("ldmatrix.sync.aligned.m8n8.x4.shared.b16 "                \
                 "{%0,%1,%2,%3}, [%4];"                                     \
                 : "=r"((r)[0]), "=r"((r)[1]), "=r"((r)[2]), "=r"((r)[3])   \
                 : "r"(a))

// Tile: 128 rows x 64 bf16 = 128B/row, XOR-swizzled in 16B chunks.
#define TILE_B   16384
#define STAGE_B  32768
#define NSTAGE   3

__device__ __forceinline__ void stage_issue(
    char* st, const __nv_bfloat16* Ag, size_t asr,
    const __nv_bfloat16* Bg, size_t bsr, int k0, int tid)
{
    #pragma unroll
    for (int j = 0; j < 4; j++) {
        int idx = j * 256 + tid;
        int row = idx >> 3;
        int ch  = idx & 7;
        int pch = ch ^ (row & 7);
        cpa16(st + row * 128 + pch * 16,          Ag + (size_t)row * asr + k0 + ch * 8);
        cpa16(st + TILE_B + row * 128 + pch * 16, Bg + (size_t)row * bsr + k0 + ch * 8);
    }
    CP_COMMIT();
}

__device__ __forceinline__ void ld_frags(
    const char* smA, const char* smB, int wm, int wn, int lr, int cg, int kg,
    uint32_t af[4][4], uint32_t bq[2][4])
{
    #pragma unroll
    for (int mt = 0; mt < 4; mt++) {
        int row = wm + mt * 16 + lr;
        int pch = (kg * 2 + cg) ^ (row & 7);
        uint32_t a = (uint32_t)__cvta_generic_to_shared(smA + row * 128 + pch * 16);
        LDSM4(af[mt], a);
    }
    #pragma unroll
    for (int pn = 0; pn < 2; pn++) {
        int row = wn + pn * 16 + lr;
        int pch = (kg * 2 + cg) ^ (row & 7);
        uint32_t a = (uint32_t)__cvta_generic_to_shared(smB + row * 128 + pch * 16);
        LDSM4(bq[pn], a);
    }
}

__device__ __forceinline__ void do_mmas(
    const uint32_t af[4][4], const uint32_t bq[2][4], float acc[4][4][4])
{
    #pragma unroll
    for (int mt = 0; mt < 4; mt++) {
        #pragma unroll
        for (int nt = 0; nt < 4; nt++) {
            const uint32_t* bp = bq[nt >> 1];
            uint32_t b0 = (nt & 1) ? bp[1] : bp[0];
            uint32_t b1 = (nt & 1) ? bp[3] : bp[2];
            MMA_BF16(acc[mt][nt], af[mt], b0, b1);
        }
    }
}

__device__ __forceinline__ void compute_buf(
    const char* smA, const char* smB,
    int wm, int wn, int lane, float acc[4][4][4])
{
    const int lr = lane & 15;
    const int cg = lane >> 4;
    uint32_t afA[4][4], bqA[2][4], afB[4][4], bqB[2][4];

    ld_frags(smA, smB, wm, wn, lr, cg, 0, afA, bqA);
    ld_frags(smA, smB, wm, wn, lr, cg, 1, afB, bqB);
    do_mmas(afA, bqA, acc);
    ld_frags(smA, smB, wm, wn, lr, cg, 2, afA, bqA);
    do_mmas(afB, bqB, acc);
    ld_frags(smA, smB, wm, wn, lr, cg, 3, afB, bqB);
    do_mmas(afA, bqA, acc);
    do_mmas(afB, bqB, acc);
}

__device__ __forceinline__ void gemm_loop(
    const __nv_bfloat16* Ag, size_t asr,
    const __nv_bfloat16* Bg, size_t bsr,
    int KT, float acc[4][4][4])
{
    extern __shared__ char dsm[];
    const int tid  = threadIdx.x;
    const int wid  = tid >> 5;
    const int lane = tid & 31;
    const int wm   = (wid & 1) * 64;
    const int wn   = (wid >> 1) * 32;

    stage_issue(dsm,           Ag, asr, Bg, bsr, 0,  tid);
    stage_issue(dsm + STAGE_B, Ag, asr, Bg, bsr, 64, tid);

    for (int i = 0; i < KT; i++) {
        if (i + 2 < KT) CP_WAIT1(); else CP_WAIT0();
        __syncthreads();
        if (i + 2 < KT) {
            char* st = dsm + ((i + 2) % 3) * STAGE_B;
            stage_issue(st, Ag, asr, Bg, bsr, (i + 2) * 64, tid);
        }
        const char* sb = dsm + (i % 3) * STAGE_B;
        compute_buf(sb, sb + TILE_B, wm, wn, lane, acc);
    }
}

// ---------------------------------------------------------------------------
// conversion kernel (x copy+convert, W convert, Z zero, unit-counter zero)
// ---------------------------------------------------------------------------
__global__ void __launch_bounds__(256) conv_all(
    const float* __restrict__ x, float* __restrict__ out,
    const float* __restrict__ Wq, const float* __restrict__ Wk,
    const float* __restrict__ Wv)
{
    size_t bi = blockIdx.x;
    if (bi == 0 && threadIdx.x == 0) g_unit = 0;
    if (bi < 2048) {
        size_t base = bi * 1024 + threadIdx.x;
        float4 a[4];
        #pragma unroll
        for (int j = 0; j < 4; j++) a[j] = ((const float4*)x)[base + j * 256];
        #pragma unroll
        for (int j = 0; j < 4; j++) {
            size_t i4 = base + j * 256;
            size_t row = i4 / 128;
            size_t c4  = i4 % 128;
            ((float4*)out)[row * 256 + c4] = a[j];
            ((__nv_bfloat162*)g_xb)[i4 * 2]     = __floats2bfloat162_rn(a[j].x, a[j].y);
            ((__nv_bfloat162*)g_xb)[i4 * 2 + 1] = __floats2bfloat162_rn(a[j].z, a[j].w);
        }
    } else if (bi < 2240) {
        size_t base = (bi - 2048) * 1024 + threadIdx.x;
        float4 a[4];
        #pragma unroll
        for (int j = 0; j < 4; j++) {
            size_t i4 = base + j * 256;
            int which = (int)(i4 >> 16);
            const float* src = (which == 0) ? Wq : (which == 1) ? Wk : Wv;
            a[j] = ((const float4*)src)[i4 & 65535];
        }
        #pragma unroll
        for (int j = 0; j < 4; j++) {
            size_t i4 = base + j * 256;
            ((__nv_bfloat162*)g_wb)[i4 * 2]     = __floats2bfloat162_rn(a[j].x, a[j].y);
            ((__nv_bfloat162*)g_wb)[i4 * 2 + 1] = __floats2bfloat162_rn(a[j].z, a[j].w);
        }
    } else {
        size_t i = (bi - 2240) * 256 + threadIdx.x;   // 16384 floats
        g_Z[i] = 0.f;
    }
}

// ---------------------------------------------------------------------------
// Kernel: q/k = x @ W^T + b  (bf16 out, row-major)
//         v   = x @ Wv^T + bv written TRANSPOSED into g_vT via smem.
// z-order flipped: V (slowest, extra transpose) launches first.
// ---------------------------------------------------------------------------
__global__ void __launch_bounds__(256, 2) qkv_kernel(
    const float* __restrict__ bq, const float* __restrict__ bk,
    const float* __restrict__ bv)
{
    const int which = 2 - blockIdx.z;    // V first
    const float* bias = (which == 0) ? bq : (which == 1) ? bk : bv;

    const int m0 = blockIdx.y * 128;
    const int n0 = blockIdx.x * 128;

    float acc[4][4][4] = {};
    gemm_loop(g_xb + (size_t)m0 * NC, NC,
              g_wb + (size_t)which * 512 * 512 + (size_t)n0 * NC, NC,
              NC / 64, acc);

    const int tid = threadIdx.x, wid = tid >> 5, lane = tid & 31;
    const int gid = lane >> 2, tig = lane & 3;
    const int wm = (wid & 1) * 64, wn = (wid >> 1) * 32;

    if (which < 2) {
        __nv_bfloat16* outp = (which == 0) ? g_qb : g_kb;
        #pragma unroll
        for (int mt = 0; mt < 4; mt++) {
            #pragma unroll
            for (int nt = 0; nt < 4; nt++) {
                int m = m0 + wm + mt * 16 + gid;
                int n = n0 + wn + nt * 8 + 2 * tig;
                float b0 = bias[n], b1 = bias[n + 1];
                __nv_bfloat162 h0 = __floats2bfloat162_rn(acc[mt][nt][0] + b0, acc[mt][nt][1] + b1);
                __nv_bfloat162 h1 = __floats2bfloat162_rn(acc[mt][nt][2] + b0, acc[mt][nt][3] + b1);
                *(__nv_bfloat162*)(outp + (size_t)m * NK + n) = h0;
                *(__nv_bfloat162*)(outp + (size_t)(m + 8) * NK + n) = h1;
            }
        }
    } else {
        // V: transpose through smem, write g_vT[(b*512+n)][t] coalesced.
        extern __shared__ char dsm[];
        __syncthreads();   // gemm done with smem
        __nv_bfloat16* ts = (__nv_bfloat16*)dsm;
        #pragma unroll
        for (int mt = 0; mt < 4; mt++) {
            #pragma unroll
            for (int nt = 0; nt < 4; nt++) {
                int ml = wm + mt * 16 + gid;
                int nl = wn + nt * 8 + 2 * tig;
                int n = n0 + nl;
                float b0 = bias[n], b1 = bias[n + 1];
                *(__nv_bfloat162*)(ts + (size_t)ml * 138 + nl) =
                    __floats2bfloat162_rn(acc[mt][nt][0] + b0, acc[mt][nt][1] + b1);
                *(__nv_bfloat162*)(ts + (size_t)(ml + 8) * 138 + nl) =
                    __floats2bfloat162_rn(acc[mt][nt][2] + b0, acc[mt][nt][3] + b1);
            }
        }
        __syncthreads();
        const int b  = m0 >> 11;
        const int t0 = m0 & 2047;
        #pragma unroll
        for (int j = 0; j < 8; j++) {
            int idx = j * 256 + tid;
            int nr = idx >> 4;
            int ch = idx & 15;
            __nv_bfloat16 tmp[8];
            #pragma unroll
            for (int e = 0; e < 8; e++)
                tmp[e] = ts[(size_t)(ch * 8 + e) * 138 + nr];
            *(uint4*)(g_vT + ((size_t)(b * NK + n0 + nr)) * NT + t0 + ch * 8) =
                *(uint4*)tmp;
        }
    }
}

// ---------------------------------------------------------------------------
// Kernel: E = exp(q @ k^T * SCALE), lower-triangle tiles (bf16 out),
// MASKED on diagonal tiles (zero for q < s), plus per-column Z accumulation.
// ---------------------------------------------------------------------------
__global__ void __launch_bounds__(256, 2) scores_kernel()
{
    const int b = blockIdx.y;
    int xi = blockIdx.x;
    int qt = (int)((sqrtf(8.0f * xi + 1.0f) - 1.0f) * 0.5f);
    while ((qt + 1) * (qt + 2) / 2 <= xi) qt++;
    while (qt * (qt + 1) / 2 > xi) qt--;
    const int st = xi - qt * (qt + 1) / 2;

    const int m0 = qt * 128;
    const int n0 = st * 128;
    const bool diag = (qt == st);

    float acc[4][4][4] = {};
    gemm_loop(g_qb + ((size_t)b * NT + m0) * NK, NK,
              g_kb + ((size_t)b * NT + n0) * NK, NK,
              NK / 64, acc);

    __nv_bfloat16* S = g_SP + (size_t)b * NT * NT;
    const int tid = threadIdx.x, wid = tid >> 5, lane = tid & 31;
    const int gid = lane >> 2, tig = lane & 3;
    const int wm = (wid & 1) * 64, wn = (wid >> 1) * 32;

    float csum[4][2];
    #pragma unroll
    for (int nt = 0; nt < 4; nt++) { csum[nt][0] = 0.f; csum[nt][1] = 0.f; }

    #pragma unroll
    for (int mt = 0; mt < 4; mt++) {
        int m = m0 + wm + mt * 16 + gid;
        #pragma unroll
        for (int nt = 0; nt < 4; nt++) {
            int n = n0 + wn + nt * 8 + 2 * tig;
            float c0 = __expf(acc[mt][nt][0] * SCALE);
            float c1 = __expf(acc[mt][nt][1] * SCALE);
            float c2 = __expf(acc[mt][nt][2] * SCALE);
            float c3 = __expf(acc[mt][nt][3] * SCALE);
            if (diag) {
                if (m < n)         c0 = 0.f;
                if (m < n + 1)     c1 = 0.f;
                if (m + 8 < n)     c2 = 0.f;
                if (m + 8 < n + 1) c3 = 0.f;
            }
            *(__nv_bfloat162*)(S + (size_t)m * NT + n)       = __floats2bfloat162_rn(c0, c1);
            *(__nv_bfloat162*)(S + (size_t)(m + 8) * NT + n) = __floats2bfloat162_rn(c2, c3);
            csum[nt][0] += c0 + c2;
            csum[nt][1] += c1 + c3;
        }
    }
    #pragma unroll
    for (int nt = 0; nt < 4; nt++) {
        #pragma unroll
        for (int c = 0; c < 2; c++) {
            float v = csum[nt][c];
            v += __shfl_xor_sync(0xffffffff, v, 4);
            v += __shfl_xor_sync(0xffffffff, v, 8);
            v += __shfl_xor_sync(0xffffffff, v, 16);
            csum[nt][c] = v;
        }
    }
    if (gid == 0) {
        #pragma unroll
        for (int nt = 0; nt < 4; nt++) {
            int n = n0 + wn + nt * 8 + 2 * tig;
            atomicAdd(&g_Z[b * NT + n],     csum[nt][0]);
            atomicAdd(&g_Z[b * NT + n + 1], csum[nt][1]);
        }
    }
}

// ---------------------------------------------------------------------------
// Kernel: g_vT[(b*512+n)][s] *= 1/Z[b][s]  (MLP=4, 1024 CTAs)
// ---------------------------------------------------------------------------
__global__ void __launch_bounds__(256) vscale_kernel()
{
    const int sb = blockIdx.x;
    const int b  = blockIdx.y;
    const int ns = blockIdx.z;
    const int s0 = sb * 64;

    __shared__ float rz[64];
    if (threadIdx.x < 64)
        rz[threadIdx.x] = 1.f / g_Z[b * NT + s0 + threadIdx.x];
    __syncthreads();

    const int tid = threadIdx.x;
    uint4 v[4];
    __nv_bfloat16* ptr[4];
    #pragma unroll
    for (int j = 0; j < 4; j++) {
        int idx = j * 256 + tid;
        int n  = ns * 128 + (idx >> 3);
        int ch = idx & 7;
        ptr[j] = g_vT + ((size_t)(b * NK + n)) * NT + s0 + ch * 8;
        v[j] = *(uint4*)ptr[j];
    }
    #pragma unroll
    for (int j = 0; j < 4; j++) {
        int idx = j * 256 + tid;
        int ch = idx & 7;
        __nv_bfloat16* e = (__nv_bfloat16*)&v[j];
        __nv_bfloat16 o[8];
        #pragma unroll
        for (int k = 0; k < 8; k++)
            o[k] = __float2bfloat16(__bfloat162float(e[k]) * rz[ch * 8 + k]);
        *(uint4*)ptr[j] = *(uint4*)o;
    }
}

// ---------------------------------------------------------------------------
// Kernel: attn = E @ V' — persistent LPT work-queue over 512 units.
// unit u: qt = 15 - u/32 (descending KT), b = (u%32)/4, n0 = (u%4)*128.
// 296 CTAs = full residency (148 SM x 2); each unit writes a disjoint
// out region -> deterministic output regardless of pop order.
// ---------------------------------------------------------------------------
__device__ __forceinline__ void attnv_tile(
    int b, int qt, int n0, float* __restrict__ out)
{
    const int m0 = qt * 128;
    const int KT = 2 * (qt + 1);

    float acc[4][4][4] = {};
    gemm_loop(g_SP + ((size_t)b * NT + m0) * NT, NT,
              g_vT + ((size_t)b * NK + n0) * NT, NT,
              KT, acc);

    const int tid = threadIdx.x, wid = tid >> 5, lane = tid & 31;
    const int gid = lane >> 2, tig = lane & 3;
    const int wm = (wid & 1) * 64, wn = (wid >> 1) * 32;

    #pragma unroll
    for (int mt = 0; mt < 4; mt++) {
        #pragma unroll
        for (int nt = 0; nt < 4; nt++) {
            int q = m0 + wm + mt * 16 + gid;
            int n = n0 + wn + nt * 8 + 2 * tig;
            float2 v0 = { acc[mt][nt][0], acc[mt][nt][1] };
            float2 v1 = { acc[mt][nt][2], acc[mt][nt][3] };
            *(float2*)(out + ((size_t)b * NT + q) * 1024 + 512 + n) = v0;
            *(float2*)(out + ((size_t)b * NT + q + 8) * 1024 + 512 + n) = v1;
        }
    }
}

__global__ void __launch_bounds__(256, 2) attnv_kernel(float* __restrict__ out)
{
    __shared__ int s_u;
    for (;;) {
        if (threadIdx.x == 0) s_u = atomicAdd(&g_unit, 1);
        __syncthreads();
        const int u = s_u;
        if (u >= 512) return;
        const int qt  = 15 - (u >> 5);
        const int sub = u & 31;
        const int b   = sub >> 2;
        const int n0  = (sub & 3) * 128;
        attnv_tile(b, qt, n0, out);
        __syncthreads();   // all threads done with s_u / smem before next pop
    }
}

// ---------------------------------------------------------------------------
extern "C" void kernel_launch(void* const* d_in, const int* in_sizes, int n_in,
                              void* d_out, int out_size)
{
    const float* x  = (const float*)d_in[0];
    const float* Wq = (const float*)d_in[1];
    const float* bq = (const float*)d_in[2];
    const float* Wk = (const float*)d_in[3];
    const float* bk = (const float*)d_in[4];
    const float* Wv = (const float*)d_in[5];
    const float* bv = (const float*)d_in[6];
    float* out = (float*)d_out;

    const int dsmem = NSTAGE * STAGE_B;  // 98304 B
    cudaFuncSetAttribute(qkv_kernel,    cudaFuncAttributeMaxDynamicSharedMemorySize, dsmem);
    cudaFuncSetAttribute(scores_kernel, cudaFuncAttributeMaxDynamicSharedMemorySize, dsmem);
    cudaFuncSetAttribute(attnv_kernel,  cudaFuncAttributeMaxDynamicSharedMemorySize, dsmem);

    conv_all<<<dim3(2304), 256>>>(x, out, Wq, Wk, Wv);
    qkv_kernel<<<dim3(4, 128, 3), 256, dsmem>>>(bq, bk, bv);
    scores_kernel<<<dim3(136, 8), 256, dsmem>>>();
    vscale_kernel<<<dim3(32, 8, 4), 256>>>();
    attnv_kernel<<<dim3(296), 256, dsmem>>>(out);
}

// round 16
// speedup vs baseline: 1.0503x; 1.0503x over previous
#include <cuda_runtime.h>
#include <cuda_bf16.h>
#include <math.h>
#include <stdint.h>

#define NB 8
#define NT 2048
#define NC 512
#define NK 512
#define SCALE 0.044194173824159216f  // 1/sqrt(512)

// Scratch (device globals: allocation-free per harness rules)
static __device__ __nv_bfloat16 g_xb[(size_t)NB * NT * NC];
static __device__ __nv_bfloat16 g_wb[3 * 512 * 512];
static __device__ __nv_bfloat16 g_qb[(size_t)NB * NT * NK];
static __device__ __nv_bfloat16 g_kb[(size_t)NB * NT * NK];
static __device__ __nv_bfloat16 g_vT[(size_t)NB * NK * NT];  // [b*512+n][s], scaled by 1/Z
static __device__ __nv_bfloat16 g_SP[(size_t)NB * NT * NT];  // bf16 E=exp(S) (masked on diag tiles)
static __device__ float         g_Z [(size_t)NB * NT];       // column sums of exp

// ---------------------------------------------------------------------------
// helpers
// ---------------------------------------------------------------------------
__device__ __forceinline__ void cpa16(void* dst_smem, const void* src) {
    unsigned s = (unsigned)__cvta_generic_to_shared(dst_smem);
    asm volatile("cp.async.cg.shared.global [%0], [%1], 16;\n" :: "r"(s), "l"(src));
}
#define CP_COMMIT() asm volatile("cp.async.commit_group;\n" ::: "memory")
#define CP_WAIT0()  asm volatile("cp.async.wait_group 0;\n" ::: "memory")
#define CP_WAIT1()  asm volatile("cp.async.wait_group 1;\n" ::: "memory")

#define MMA_BF16(c, a, b0, b1)                                              \
    asm volatile(                                                           \
        "mma.sync.aligned.m16n8k16.row.col.f32.bf16.bf16.f32 "              \
        "{%0,%1,%2,%3},{%4,%5,%6,%7},{%8,%9},{%0,%1,%2,%3};\n"              \
        : "+f"((c)[0]), "+f"((c)[1]), "+f"((c)[2]), "+f"((c)[3])            \
        : "r"((a)[0]), "r"((a)[1]), "r"((a)[2]), "r"((a)[3]),               \
          "r"(b0), "r"(b1))

#define LDSM4(r, a)                                                         \
    asm volatile("ldmatrix.sync.aligned.m8n8.x4.shared.b16 "                \
                 "{%0,%1,%2,%3}, [%4];"                                     \
                 : "=r"((r)[0]), "=r"((r)[1]), "=r"((r)[2]), "=r"((r)[3])   \
                 : "r"(a))

// Tile: 128 rows x 64 bf16 = 128B/row, XOR-swizzled in 16B chunks.
#define TILE_B   16384
#define STAGE_B  32768
#define NSTAGE   3

__device__ __forceinline__ void stage_issue(
    char* st, const __nv_bfloat16* Ag, size_t asr,
    const __nv_bfloat16* Bg, size_t bsr, int k0, int tid)
{
    #pragma unroll
    for (int j = 0; j < 4; j++) {
        int idx = j * 256 + tid;
        int row = idx >> 3;
        int ch  = idx & 7;
        int pch = ch ^ (row & 7);
        cpa16(st + row * 128 + pch * 16,          Ag + (size_t)row * asr + k0 + ch * 8);
        cpa16(st + TILE_B + row * 128 + pch * 16, Bg + (size_t)row * bsr + k0 + ch * 8);
    }
    CP_COMMIT();
}

__device__ __forceinline__ void ld_frags(
    const char* smA, const char* smB, int wm, int wn, int lr, int cg, int kg,
    uint32_t af[4][4], uint32_t bq[2][4])
{
    #pragma unroll
    for (int mt = 0; mt < 4; mt++) {
        int row = wm + mt * 16 + lr;
        int pch = (kg * 2 + cg) ^ (row & 7);
        uint32_t a = (uint32_t)__cvta_generic_to_shared(smA + row * 128 + pch * 16);
        LDSM4(af[mt], a);
    }
    #pragma unroll
    for (int pn = 0; pn < 2; pn++) {
        int row = wn + pn * 16 + lr;
        int pch = (kg * 2 + cg) ^ (row & 7);
        uint32_t a = (uint32_t)__cvta_generic_to_shared(smB + row * 128 + pch * 16);
        LDSM4(bq[pn], a);
    }
}

__device__ __forceinline__ void do_mmas(
    const uint32_t af[4][4], const uint32_t bq[2][4], float acc[4][4][4])
{
    #pragma unroll
    for (int mt = 0; mt < 4; mt++) {
        #pragma unroll
        for (int nt = 0; nt < 4; nt++) {
            const uint32_t* bp = bq[nt >> 1];
            uint32_t b0 = (nt & 1) ? bp[1] : bp[0];
            uint32_t b1 = (nt & 1) ? bp[3] : bp[2];
            MMA_BF16(acc[mt][nt], af[mt], b0, b1);
        }
    }
}

__device__ __forceinline__ void compute_buf(
    const char* smA, const char* smB,
    int wm, int wn, int lane, float acc[4][4][4])
{
    const int lr = lane & 15;
    const int cg = lane >> 4;
    uint32_t afA[4][4], bqA[2][4], afB[4][4], bqB[2][4];

    ld_frags(smA, smB, wm, wn, lr, cg, 0, afA, bqA);
    ld_frags(smA, smB, wm, wn, lr, cg, 1, afB, bqB);
    do_mmas(afA, bqA, acc);
    ld_frags(smA, smB, wm, wn, lr, cg, 2, afA, bqA);
    do_mmas(afB, bqB, acc);
    ld_frags(smA, smB, wm, wn, lr, cg, 3, afB, bqB);
    do_mmas(afA, bqA, acc);
    do_mmas(afB, bqB, acc);
}

__device__ __forceinline__ void gemm_loop(
    const __nv_bfloat16* Ag, size_t asr,
    const __nv_bfloat16* Bg, size_t bsr,
    int KT, float acc[4][4][4])
{
    extern __shared__ char dsm[];
    const int tid  = threadIdx.x;
    const int wid  = tid >> 5;
    const int lane = tid & 31;
    const int wm   = (wid & 1) * 64;
    const int wn   = (wid >> 1) * 32;

    stage_issue(dsm,           Ag, asr, Bg, bsr, 0,  tid);
    stage_issue(dsm + STAGE_B, Ag, asr, Bg, bsr, 64, tid);

    for (int i = 0; i < KT; i++) {
        if (i + 2 < KT) CP_WAIT1(); else CP_WAIT0();
        __syncthreads();
        if (i + 2 < KT) {
            char* st = dsm + ((i + 2) % 3) * STAGE_B;
            stage_issue(st, Ag, asr, Bg, bsr, (i + 2) * 64, tid);
        }
        const char* sb = dsm + (i % 3) * STAGE_B;
        compute_buf(sb, sb + TILE_B, wm, wn, lane, acc);
    }
}

// ---------------------------------------------------------------------------
// conversion kernel (x copy+convert, W convert, Z zero) — merged, MLP=4
// ---------------------------------------------------------------------------
__global__ void __launch_bounds__(256) conv_all(
    const float* __restrict__ x, float* __restrict__ out,
    const float* __restrict__ Wq, const float* __restrict__ Wk,
    const float* __restrict__ Wv)
{
    size_t bi = blockIdx.x;
    if (bi < 2048) {
        size_t base = bi * 1024 + threadIdx.x;
        float4 a[4];
        #pragma unroll
        for (int j = 0; j < 4; j++) a[j] = ((const float4*)x)[base + j * 256];
        #pragma unroll
        for (int j = 0; j < 4; j++) {
            size_t i4 = base + j * 256;
            size_t row = i4 / 128;
            size_t c4  = i4 % 128;
            ((float4*)out)[row * 256 + c4] = a[j];
            ((__nv_bfloat162*)g_xb)[i4 * 2]     = __floats2bfloat162_rn(a[j].x, a[j].y);
            ((__nv_bfloat162*)g_xb)[i4 * 2 + 1] = __floats2bfloat162_rn(a[j].z, a[j].w);
        }
    } else if (bi < 2240) {
        size_t base = (bi - 2048) * 1024 + threadIdx.x;
        float4 a[4];
        #pragma unroll
        for (int j = 0; j < 4; j++) {
            size_t i4 = base + j * 256;
            int which = (int)(i4 >> 16);
            const float* src = (which == 0) ? Wq : (which == 1) ? Wk : Wv;
            a[j] = ((const float4*)src)[i4 & 65535];
        }
        #pragma unroll
        for (int j = 0; j < 4; j++) {
            size_t i4 = base + j * 256;
            ((__nv_bfloat162*)g_wb)[i4 * 2]     = __floats2bfloat162_rn(a[j].x, a[j].y);
            ((__nv_bfloat162*)g_wb)[i4 * 2 + 1] = __floats2bfloat162_rn(a[j].z, a[j].w);
        }
    } else {
        size_t i = (bi - 2240) * 256 + threadIdx.x;   // 16384 floats
        g_Z[i] = 0.f;
    }
}

// ---------------------------------------------------------------------------
// Kernel: q/k = x @ W^T + b  (bf16 out, row-major)
//         v   = x @ Wv^T + bv written TRANSPOSED into g_vT via smem.
// z-order: V (slowest, extra transpose epilogue) launches first.
// ---------------------------------------------------------------------------
__global__ void __launch_bounds__(256, 2) qkv_kernel(
    const float* __restrict__ bq, const float* __restrict__ bk,
    const float* __restrict__ bv)
{
    const int which = 2 - blockIdx.z;    // V first
    const float* bias = (which == 0) ? bq : (which == 1) ? bk : bv;

    const int m0 = blockIdx.y * 128;
    const int n0 = blockIdx.x * 128;

    float acc[4][4][4] = {};
    gemm_loop(g_xb + (size_t)m0 * NC, NC,
              g_wb + (size_t)which * 512 * 512 + (size_t)n0 * NC, NC,
              NC / 64, acc);

    const int tid = threadIdx.x, wid = tid >> 5, lane = tid & 31;
    const int gid = lane >> 2, tig = lane & 3;
    const int wm = (wid & 1) * 64, wn = (wid >> 1) * 32;

    if (which < 2) {
        __nv_bfloat16* outp = (which == 0) ? g_qb : g_kb;
        #pragma unroll
        for (int mt = 0; mt < 4; mt++) {
            #pragma unroll
            for (int nt = 0; nt < 4; nt++) {
                int m = m0 + wm + mt * 16 + gid;
                int n = n0 + wn + nt * 8 + 2 * tig;
                float b0 = bias[n], b1 = bias[n + 1];
                __nv_bfloat162 h0 = __floats2bfloat162_rn(acc[mt][nt][0] + b0, acc[mt][nt][1] + b1);
                __nv_bfloat162 h1 = __floats2bfloat162_rn(acc[mt][nt][2] + b0, acc[mt][nt][3] + b1);
                *(__nv_bfloat162*)(outp + (size_t)m * NK + n) = h0;
                *(__nv_bfloat162*)(outp + (size_t)(m + 8) * NK + n) = h1;
            }
        }
    } else {
        // V: transpose through smem, write g_vT[(b*512+n)][t] coalesced.
        extern __shared__ char dsm[];
        __syncthreads();   // gemm done with smem
        __nv_bfloat16* ts = (__nv_bfloat16*)dsm;
        #pragma unroll
        for (int mt = 0; mt < 4; mt++) {
            #pragma unroll
            for (int nt = 0; nt < 4; nt++) {
                int ml = wm + mt * 16 + gid;
                int nl = wn + nt * 8 + 2 * tig;
                int n = n0 + nl;
                float b0 = bias[n], b1 = bias[n + 1];
                *(__nv_bfloat162*)(ts + (size_t)ml * 138 + nl) =
                    __floats2bfloat162_rn(acc[mt][nt][0] + b0, acc[mt][nt][1] + b1);
                *(__nv_bfloat162*)(ts + (size_t)(ml + 8) * 138 + nl) =
                    __floats2bfloat162_rn(acc[mt][nt][2] + b0, acc[mt][nt][3] + b1);
            }
        }
        __syncthreads();
        const int b  = m0 >> 11;
        const int t0 = m0 & 2047;
        #pragma unroll
        for (int j = 0; j < 8; j++) {
            int idx = j * 256 + tid;
            int nr = idx >> 4;
            int ch = idx & 15;
            __nv_bfloat16 tmp[8];
            #pragma unroll
            for (int e = 0; e < 8; e++)
                tmp[e] = ts[(size_t)(ch * 8 + e) * 138 + nr];
            *(uint4*)(g_vT + ((size_t)(b * NK + n0 + nr)) * NT + t0 + ch * 8) =
                *(uint4*)tmp;
        }
    }
}

// ---------------------------------------------------------------------------
// Kernel: E = exp(q @ k^T * SCALE), lower-triangle tiles (bf16 out),
// MASKED on diagonal tiles (zero for q < s), plus per-column Z accumulation.
// ---------------------------------------------------------------------------
__global__ void __launch_bounds__(256, 2) scores_kernel()
{
    const int b = blockIdx.y;
    int xi = blockIdx.x;
    int qt = (int)((sqrtf(8.0f * xi + 1.0f) - 1.0f) * 0.5f);
    while ((qt + 1) * (qt + 2) / 2 <= xi) qt++;
    while (qt * (qt + 1) / 2 > xi) qt--;
    const int st = xi - qt * (qt + 1) / 2;

    const int m0 = qt * 128;
    const int n0 = st * 128;
    const bool diag = (qt == st);

    float acc[4][4][4] = {};
    gemm_loop(g_qb + ((size_t)b * NT + m0) * NK, NK,
              g_kb + ((size_t)b * NT + n0) * NK, NK,
              NK / 64, acc);

    __nv_bfloat16* S = g_SP + (size_t)b * NT * NT;
    const int tid = threadIdx.x, wid = tid >> 5, lane = tid & 31;
    const int gid = lane >> 2, tig = lane & 3;
    const int wm = (wid & 1) * 64, wn = (wid >> 1) * 32;

    float csum[4][2];
    #pragma unroll
    for (int nt = 0; nt < 4; nt++) { csum[nt][0] = 0.f; csum[nt][1] = 0.f; }

    #pragma unroll
    for (int mt = 0; mt < 4; mt++) {
        int m = m0 + wm + mt * 16 + gid;
        #pragma unroll
        for (int nt = 0; nt < 4; nt++) {
            int n = n0 + wn + nt * 8 + 2 * tig;
            float c0 = __expf(acc[mt][nt][0] * SCALE);
            float c1 = __expf(acc[mt][nt][1] * SCALE);
            float c2 = __expf(acc[mt][nt][2] * SCALE);
            float c3 = __expf(acc[mt][nt][3] * SCALE);
            if (diag) {
                if (m < n)         c0 = 0.f;
                if (m < n + 1)     c1 = 0.f;
                if (m + 8 < n)     c2 = 0.f;
                if (m + 8 < n + 1) c3 = 0.f;
            }
            *(__nv_bfloat162*)(S + (size_t)m * NT + n)       = __floats2bfloat162_rn(c0, c1);
            *(__nv_bfloat162*)(S + (size_t)(m + 8) * NT + n) = __floats2bfloat162_rn(c2, c3);
            csum[nt][0] += c0 + c2;
            csum[nt][1] += c1 + c3;
        }
    }
    #pragma unroll
    for (int nt = 0; nt < 4; nt++) {
        #pragma unroll
        for (int c = 0; c < 2; c++) {
            float v = csum[nt][c];
            v += __shfl_xor_sync(0xffffffff, v, 4);
            v += __shfl_xor_sync(0xffffffff, v, 8);
            v += __shfl_xor_sync(0xffffffff, v, 16);
            csum[nt][c] = v;
        }
    }
    if (gid == 0) {
        #pragma unroll
        for (int nt = 0; nt < 4; nt++) {
            int n = n0 + wn + nt * 8 + 2 * tig;
            atomicAdd(&g_Z[b * NT + n],     csum[nt][0]);
            atomicAdd(&g_Z[b * NT + n + 1], csum[nt][1]);
        }
    }
}

// ---------------------------------------------------------------------------
// Kernel: g_vT[(b*512+n)][s] *= 1/Z[b][s]  (MLP=4, 1024 CTAs)
// ---------------------------------------------------------------------------
__global__ void __launch_bounds__(256) vscale_kernel()
{
    const int sb = blockIdx.x;
    const int b  = blockIdx.y;
    const int ns = blockIdx.z;
    const int s0 = sb * 64;

    __shared__ float rz[64];
    if (threadIdx.x < 64)
        rz[threadIdx.x] = 1.f / g_Z[b * NT + s0 + threadIdx.x];
    __syncthreads();

    const int tid = threadIdx.x;
    uint4 v[4];
    __nv_bfloat16* ptr[4];
    #pragma unroll
    for (int j = 0; j < 4; j++) {
        int idx = j * 256 + tid;
        int n  = ns * 128 + (idx >> 3);
        int ch = idx & 7;
        ptr[j] = g_vT + ((size_t)(b * NK + n)) * NT + s0 + ch * 8;
        v[j] = *(uint4*)ptr[j];
    }
    #pragma unroll
    for (int j = 0; j < 4; j++) {
        int idx = j * 256 + tid;
        int ch = idx & 7;
        __nv_bfloat16* e = (__nv_bfloat16*)&v[j];
        __nv_bfloat16 o[8];
        #pragma unroll
        for (int k = 0; k < 8; k++)
            o[k] = __float2bfloat16(__bfloat162float(e[k]) * rz[ch * 8 + k]);
        *(uint4*)ptr[j] = *(uint4*)o;
    }
}

// ---------------------------------------------------------------------------
// Kernel: attn = E @ V' (B = scaled g_vT). Complementary-pair scheduling:
// each CTA does (15 - py, py): uniform 34 k64 iters, 256 CTAs <= one wave.
// ---------------------------------------------------------------------------
__device__ __forceinline__ void attnv_tile(
    int b, int qt, int n0, float* __restrict__ out)
{
    const int m0 = qt * 128;
    const int KT = 2 * (qt + 1);

    float acc[4][4][4] = {};
    gemm_loop(g_SP + ((size_t)b * NT + m0) * NT, NT,
              g_vT + ((size_t)b * NK + n0) * NT, NT,
              KT, acc);

    const int tid = threadIdx.x, wid = tid >> 5, lane = tid & 31;
    const int gid = lane >> 2, tig = lane & 3;
    const int wm = (wid & 1) * 64, wn = (wid >> 1) * 32;

    #pragma unroll
    for (int mt = 0; mt < 4; mt++) {
        #pragma unroll
        for (int nt = 0; nt < 4; nt++) {
            int q = m0 + wm + mt * 16 + gid;
            int n = n0 + wn + nt * 8 + 2 * tig;
            float2 v0 = { acc[mt][nt][0], acc[mt][nt][1] };
            float2 v1 = { acc[mt][nt][2], acc[mt][nt][3] };
            *(float2*)(out + ((size_t)b * NT + q) * 1024 + 512 + n) = v0;
            *(float2*)(out + ((size_t)b * NT + q + 8) * 1024 + 512 + n) = v1;
        }
    }
}

__global__ void __launch_bounds__(256, 2) attnv_kernel(float* __restrict__ out)
{
    const int b  = blockIdx.z;
    const int py = blockIdx.y;
    const int n0 = blockIdx.x * 128;

    attnv_tile(b, 15 - py, n0, out);    // big tile first
    __syncthreads();                    // smem reuse barrier between tiles
    attnv_tile(b, py, n0, out);
}

// ---------------------------------------------------------------------------
extern "C" void kernel_launch(void* const* d_in, const int* in_sizes, int n_in,
                              void* d_out, int out_size)
{
    const float* x  = (const float*)d_in[0];
    const float* Wq = (const float*)d_in[1];
    const float* bq = (const float*)d_in[2];
    const float* Wk = (const float*)d_in[3];
    const float* bk = (const float*)d_in[4];
    const float* Wv = (const float*)d_in[5];
    const float* bv = (const float*)d_in[6];
    float* out = (float*)d_out;

    const int dsmem = NSTAGE * STAGE_B;  // 98304 B
    cudaFuncSetAttribute(qkv_kernel,    cudaFuncAttributeMaxDynamicSharedMemorySize, dsmem);
    cudaFuncSetAttribute(scores_kernel, cudaFuncAttributeMaxDynamicSharedMemorySize, dsmem);
    cudaFuncSetAttribute(attnv_kernel,  cudaFuncAttributeMaxDynamicSharedMemorySize, dsmem);

    conv_all<<<dim3(2304), 256>>>(x, out, Wq, Wk, Wv);
    qkv_kernel<<<dim3(4, 128, 3), 256, dsmem>>>(bq, bk, bv);
    scores_kernel<<<dim3(136, 8), 256, dsmem>>>();
    vscale_kernel<<<dim3(32, 8, 4), 256>>>();
    attnv_kernel<<<dim3(4, 8, 8), 256, dsmem>>>(out);
}

// round 17
// speedup vs baseline: 1.0898x; 1.0376x over previous
#include <cuda_runtime.h>
#include <cuda_bf16.h>
#include <math.h>
#include <stdint.h>

#define NB 8
#define NT 2048
#define NC 512
#define NK 512
#define SCALE 0.044194173824159216f  // 1/sqrt(512)

// Scratch (device globals: allocation-free per harness rules)
static __device__ __nv_bfloat16 g_xb[(size_t)NB * NT * NC];
static __device__ __nv_bfloat16 g_wb[3 * 512 * 512];
static __device__ __nv_bfloat16 g_qb[(size_t)NB * NT * NK];
static __device__ __nv_bfloat16 g_kb[(size_t)NB * NT * NK];
static __device__ __nv_bfloat16 g_vT[(size_t)NB * NK * NT];  // [b*512+n][s], scaled by 1/Z
static __device__ __nv_bfloat16 g_SP[(size_t)NB * NT * NT];  // bf16 E=exp(S) (masked on diag tiles)
static __device__ float         g_Z [(size_t)NB * NT];       // column sums of exp

// ---------------------------------------------------------------------------
// helpers
// ---------------------------------------------------------------------------
__device__ __forceinline__ void cpa16(void* dst_smem, const void* src) {
    unsigned s = (unsigned)__cvta_generic_to_shared(dst_smem);
    asm volatile("cp.async.cg.shared.global [%0], [%1], 16;\n" :: "r"(s), "l"(src));
}
#define CP_COMMIT() asm volatile("cp.async.commit_group;\n" ::: "memory")
#define CP_WAIT0()  asm volatile("cp.async.wait_group 0;\n" ::: "memory")
#define CP_WAIT1()  asm volatile("cp.async.wait_group 1;\n" ::: "memory")

#define MMA_BF16(c, a, b0, b1)                                              \
    asm volatile(                                                           \
        "mma.sync.aligned.m16n8k16.row.col.f32.bf16.bf16.f32 "              \
        "{%0,%1,%2,%3},{%4,%5,%6,%7},{%8,%9},{%0,%1,%2,%3};\n"              \
        : "+f"((c)[0]), "+f"((c)[1]), "+f"((c)[2]), "+f"((c)[3])            \
        : "r"((a)[0]), "r"((a)[1]), "r"((a)[2]), "r"((a)[3]),               \
          "r"(b0), "r"(b1))

#define LDSM4(r, a)                                                         \
    asm volatile("ldmatrix.sync.aligned.m8n8.x4.shared.b16 "                \
                 "{%0,%1,%2,%3}, [%4];"                                     \
                 : "=r"((r)[0]), "=r"((r)[1]), "=r"((r)[2]), "=r"((r)[3])   \
                 : "r"(a))

// Tile: 128 rows x 64 bf16 = 128B/row, XOR-swizzled in 16B chunks.
#define TILE_B   16384
#define STAGE_B  32768
#define NSTAGE   3

__device__ __forceinline__ void stage_issue(
    char* st, const __nv_bfloat16* Ag, size_t asr,
    const __nv_bfloat16* Bg, size_t bsr, int k0, int tid)
{
    #pragma unroll
    for (int j = 0; j < 4; j++) {
        int idx = j * 256 + tid;
        int row = idx >> 3;
        int ch  = idx & 7;
        int pch = ch ^ (row & 7);
        cpa16(st + row * 128 + pch * 16,          Ag + (size_t)row * asr + k0 + ch * 8);
        cpa16(st + TILE_B + row * 128 + pch * 16, Bg + (size_t)row * bsr + k0 + ch * 8);
    }
    CP_COMMIT();
}

__device__ __forceinline__ void ld_frags(
    const char* smA, const char* smB, int wm, int wn, int lr, int cg, int kg,
    uint32_t af[4][4], uint32_t bq[2][4])
{
    #pragma unroll
    for (int mt = 0; mt < 4; mt++) {
        int row = wm + mt * 16 + lr;
        int pch = (kg * 2 + cg) ^ (row & 7);
        uint32_t a = (uint32_t)__cvta_generic_to_shared(smA + row * 128 + pch * 16);
        LDSM4(af[mt], a);
    }
    #pragma unroll
    for (int pn = 0; pn < 2; pn++) {
        int row = wn + pn * 16 + lr;
        int pch = (kg * 2 + cg) ^ (row & 7);
        uint32_t a = (uint32_t)__cvta_generic_to_shared(smB + row * 128 + pch * 16);
        LDSM4(bq[pn], a);
    }
}

__device__ __forceinline__ void do_mmas(
    const uint32_t af[4][4], const uint32_t bq[2][4], float acc[4][4][4])
{
    #pragma unroll
    for (int mt = 0; mt < 4; mt++) {
        #pragma unroll
        for (int nt = 0; nt < 4; nt++) {
            const uint32_t* bp = bq[nt >> 1];
            uint32_t b0 = (nt & 1) ? bp[1] : bp[0];
            uint32_t b1 = (nt & 1) ? bp[3] : bp[2];
            MMA_BF16(acc[mt][nt], af[mt], b0, b1);
        }
    }
}

__device__ __forceinline__ void compute_buf(
    const char* smA, const char* smB,
    int wm, int wn, int lane, float acc[4][4][4])
{
    const int lr = lane & 15;
    const int cg = lane >> 4;
    uint32_t afA[4][4], bqA[2][4], afB[4][4], bqB[2][4];

    ld_frags(smA, smB, wm, wn, lr, cg, 0, afA, bqA);
    ld_frags(smA, smB, wm, wn, lr, cg, 1, afB, bqB);
    do_mmas(afA, bqA, acc);
    ld_frags(smA, smB, wm, wn, lr, cg, 2, afA, bqA);
    do_mmas(afB, bqB, acc);
    ld_frags(smA, smB, wm, wn, lr, cg, 3, afB, bqB);
    do_mmas(afA, bqA, acc);
    do_mmas(afB, bqB, acc);
}

__device__ __forceinline__ void gemm_loop(
    const __nv_bfloat16* Ag, size_t asr,
    const __nv_bfloat16* Bg, size_t bsr,
    int KT, float acc[4][4][4])
{
    extern __shared__ char dsm[];
    const int tid  = threadIdx.x;
    const int wid  = tid >> 5;
    const int lane = tid & 31;
    const int wm   = (wid & 1) * 64;
    const int wn   = (wid >> 1) * 32;

    stage_issue(dsm,           Ag, asr, Bg, bsr, 0,  tid);
    stage_issue(dsm + STAGE_B, Ag, asr, Bg, bsr, 64, tid);

    for (int i = 0; i < KT; i++) {
        if (i + 2 < KT) CP_WAIT1(); else CP_WAIT0();
        __syncthreads();
        if (i + 2 < KT) {
            char* st = dsm + ((i + 2) % 3) * STAGE_B;
            stage_issue(st, Ag, asr, Bg, bsr, (i + 2) * 64, tid);
        }
        const char* sb = dsm + (i % 3) * STAGE_B;
        compute_buf(sb, sb + TILE_B, wm, wn, lane, acc);
    }
}

// ---------------------------------------------------------------------------
// conversion kernel (x copy+convert, W convert, Z zero) — merged, MLP=4
// ---------------------------------------------------------------------------
__global__ void __launch_bounds__(256) conv_all(
    const float* __restrict__ x, float* __restrict__ out,
    const float* __restrict__ Wq, const float* __restrict__ Wk,
    const float* __restrict__ Wv)
{
    size_t bi = blockIdx.x;
    if (bi < 2048) {
        size_t base = bi * 1024 + threadIdx.x;
        float4 a[4];
        #pragma unroll
        for (int j = 0; j < 4; j++) a[j] = ((const float4*)x)[base + j * 256];
        #pragma unroll
        for (int j = 0; j < 4; j++) {
            size_t i4 = base + j * 256;
            size_t row = i4 / 128;
            size_t c4  = i4 % 128;
            ((float4*)out)[row * 256 + c4] = a[j];
            ((__nv_bfloat162*)g_xb)[i4 * 2]     = __floats2bfloat162_rn(a[j].x, a[j].y);
            ((__nv_bfloat162*)g_xb)[i4 * 2 + 1] = __floats2bfloat162_rn(a[j].z, a[j].w);
        }
    } else if (bi < 2240) {
        size_t base = (bi - 2048) * 1024 + threadIdx.x;
        float4 a[4];
        #pragma unroll
        for (int j = 0; j < 4; j++) {
            size_t i4 = base + j * 256;
            int which = (int)(i4 >> 16);
            const float* src = (which == 0) ? Wq : (which == 1) ? Wk : Wv;
            a[j] = ((const float4*)src)[i4 & 65535];
        }
        #pragma unroll
        for (int j = 0; j < 4; j++) {
            size_t i4 = base + j * 256;
            ((__nv_bfloat162*)g_wb)[i4 * 2]     = __floats2bfloat162_rn(a[j].x, a[j].y);
            ((__nv_bfloat162*)g_wb)[i4 * 2 + 1] = __floats2bfloat162_rn(a[j].z, a[j].w);
        }
    } else {
        size_t i = (bi - 2240) * 256 + threadIdx.x;   // 16384 floats
        g_Z[i] = 0.f;
    }
}

// ---------------------------------------------------------------------------
// Kernel: q/k = x @ W^T + b  (bf16 out, row-major)
// ---------------------------------------------------------------------------
__global__ void __launch_bounds__(256, 2) qk_kernel(
    const float* __restrict__ bq, const float* __restrict__ bk)
{
    const int which = blockIdx.z;        // 0=q, 1=k
    const float* bias = (which == 0) ? bq : bk;
    __nv_bfloat16* outp = (which == 0) ? g_qb : g_kb;

    const int m0 = blockIdx.y * 128;
    const int n0 = blockIdx.x * 128;

    float acc[4][4][4] = {};
    gemm_loop(g_xb + (size_t)m0 * NC, NC,
              g_wb + (size_t)which * 512 * 512 + (size_t)n0 * NC, NC,
              NC / 64, acc);

    const int tid = threadIdx.x, wid = tid >> 5, lane = tid & 31;
    const int gid = lane >> 2, tig = lane & 3;
    const int wm = (wid & 1) * 64, wn = (wid >> 1) * 32;

    #pragma unroll
    for (int mt = 0; mt < 4; mt++) {
        #pragma unroll
        for (int nt = 0; nt < 4; nt++) {
            int m = m0 + wm + mt * 16 + gid;
            int n = n0 + wn + nt * 8 + 2 * tig;
            float b0 = bias[n], b1 = bias[n + 1];
            __nv_bfloat162 h0 = __floats2bfloat162_rn(acc[mt][nt][0] + b0, acc[mt][nt][1] + b1);
            __nv_bfloat162 h1 = __floats2bfloat162_rn(acc[mt][nt][2] + b0, acc[mt][nt][3] + b1);
            *(__nv_bfloat162*)(outp + (size_t)m * NK + n) = h0;
            *(__nv_bfloat162*)(outp + (size_t)(m + 8) * NK + n) = h1;
        }
    }
}

// ---------------------------------------------------------------------------
// Kernel: v = x @ Wv^T + bv written TRANSPOSED into g_vT via smem.
// Runs on a forked stream, concurrent with qk/scores.
// ---------------------------------------------------------------------------
__global__ void __launch_bounds__(256, 2) v_kernel(const float* __restrict__ bv)
{
    const int m0 = blockIdx.y * 128;
    const int n0 = blockIdx.x * 128;

    float acc[4][4][4] = {};
    gemm_loop(g_xb + (size_t)m0 * NC, NC,
              g_wb + (size_t)2 * 512 * 512 + (size_t)n0 * NC, NC,
              NC / 64, acc);

    const int tid = threadIdx.x, wid = tid >> 5, lane = tid & 31;
    const int gid = lane >> 2, tig = lane & 3;
    const int wm = (wid & 1) * 64, wn = (wid >> 1) * 32;

    extern __shared__ char dsm[];
    __syncthreads();   // gemm done with smem
    __nv_bfloat16* ts = (__nv_bfloat16*)dsm;
    #pragma unroll
    for (int mt = 0; mt < 4; mt++) {
        #pragma unroll
        for (int nt = 0; nt < 4; nt++) {
            int ml = wm + mt * 16 + gid;
            int nl = wn + nt * 8 + 2 * tig;
            int n = n0 + nl;
            float b0 = bv[n], b1 = bv[n + 1];
            *(__nv_bfloat162*)(ts + (size_t)ml * 138 + nl) =
                __floats2bfloat162_rn(acc[mt][nt][0] + b0, acc[mt][nt][1] + b1);
            *(__nv_bfloat162*)(ts + (size_t)(ml + 8) * 138 + nl) =
                __floats2bfloat162_rn(acc[mt][nt][2] + b0, acc[mt][nt][3] + b1);
        }
    }
    __syncthreads();
    const int b  = m0 >> 11;
    const int t0 = m0 & 2047;
    #pragma unroll
    for (int j = 0; j < 8; j++) {
        int idx = j * 256 + tid;
        int nr = idx >> 4;
        int ch = idx & 15;
        __nv_bfloat16 tmp[8];
        #pragma unroll
        for (int e = 0; e < 8; e++)
            tmp[e] = ts[(size_t)(ch * 8 + e) * 138 + nr];
        *(uint4*)(g_vT + ((size_t)(b * NK + n0 + nr)) * NT + t0 + ch * 8) =
            *(uint4*)tmp;
    }
}

// ---------------------------------------------------------------------------
// Kernel: E = exp(q @ k^T * SCALE), lower-triangle tiles (bf16 out),
// MASKED on diagonal tiles (zero for q < s), plus per-column Z accumulation.
// ---------------------------------------------------------------------------
__global__ void __launch_bounds__(256, 2) scores_kernel()
{
    const int b = blockIdx.y;
    int xi = blockIdx.x;
    int qt = (int)((sqrtf(8.0f * xi + 1.0f) - 1.0f) * 0.5f);
    while ((qt + 1) * (qt + 2) / 2 <= xi) qt++;
    while (qt * (qt + 1) / 2 > xi) qt--;
    const int st = xi - qt * (qt + 1) / 2;

    const int m0 = qt * 128;
    const int n0 = st * 128;
    const bool diag = (qt == st);

    float acc[4][4][4] = {};
    gemm_loop(g_qb + ((size_t)b * NT + m0) * NK, NK,
              g_kb + ((size_t)b * NT + n0) * NK, NK,
              NK / 64, acc);

    __nv_bfloat16* S = g_SP + (size_t)b * NT * NT;
    const int tid = threadIdx.x, wid = tid >> 5, lane = tid & 31;
    const int gid = lane >> 2, tig = lane & 3;
    const int wm = (wid & 1) * 64, wn = (wid >> 1) * 32;

    float csum[4][2];
    #pragma unroll
    for (int nt = 0; nt < 4; nt++) { csum[nt][0] = 0.f; csum[nt][1] = 0.f; }

    #pragma unroll
    for (int mt = 0; mt < 4; mt++) {
        int m = m0 + wm + mt * 16 + gid;
        #pragma unroll
        for (int nt = 0; nt < 4; nt++) {
            int n = n0 + wn + nt * 8 + 2 * tig;
            float c0 = __expf(acc[mt][nt][0] * SCALE);
            float c1 = __expf(acc[mt][nt][1] * SCALE);
            float c2 = __expf(acc[mt][nt][2] * SCALE);
            float c3 = __expf(acc[mt][nt][3] * SCALE);
            if (diag) {
                if (m < n)         c0 = 0.f;
                if (m < n + 1)     c1 = 0.f;
                if (m + 8 < n)     c2 = 0.f;
                if (m + 8 < n + 1) c3 = 0.f;
            }
            *(__nv_bfloat162*)(S + (size_t)m * NT + n)       = __floats2bfloat162_rn(c0, c1);
            *(__nv_bfloat162*)(S + (size_t)(m + 8) * NT + n) = __floats2bfloat162_rn(c2, c3);
            csum[nt][0] += c0 + c2;
            csum[nt][1] += c1 + c3;
        }
    }
    #pragma unroll
    for (int nt = 0; nt < 4; nt++) {
        #pragma unroll
        for (int c = 0; c < 2; c++) {
            float v = csum[nt][c];
            v += __shfl_xor_sync(0xffffffff, v, 4);
            v += __shfl_xor_sync(0xffffffff, v, 8);
            v += __shfl_xor_sync(0xffffffff, v, 16);
            csum[nt][c] = v;
        }
    }
    if (gid == 0) {
        #pragma unroll
        for (int nt = 0; nt < 4; nt++) {
            int n = n0 + wn + nt * 8 + 2 * tig;
            atomicAdd(&g_Z[b * NT + n],     csum[nt][0]);
            atomicAdd(&g_Z[b * NT + n + 1], csum[nt][1]);
        }
    }
}

// ---------------------------------------------------------------------------
// Kernel: g_vT[(b*512+n)][s] *= 1/Z[b][s]  (MLP=4, 1024 CTAs)
// ---------------------------------------------------------------------------
__global__ void __launch_bounds__(256) vscale_kernel()
{
    const int sb = blockIdx.x;
    const int b  = blockIdx.y;
    const int ns = blockIdx.z;
    const int s0 = sb * 64;

    __shared__ float rz[64];
    if (threadIdx.x < 64)
        rz[threadIdx.x] = 1.f / g_Z[b * NT + s0 + threadIdx.x];
    __syncthreads();

    const int tid = threadIdx.x;
    uint4 v[4];
    __nv_bfloat16* ptr[4];
    #pragma unroll
    for (int j = 0; j < 4; j++) {
        int idx = j * 256 + tid;
        int n  = ns * 128 + (idx >> 3);
        int ch = idx & 7;
        ptr[j] = g_vT + ((size_t)(b * NK + n)) * NT + s0 + ch * 8;
        v[j] = *(uint4*)ptr[j];
    }
    #pragma unroll
    for (int j = 0; j < 4; j++) {
        int idx = j * 256 + tid;
        int ch = idx & 7;
        __nv_bfloat16* e = (__nv_bfloat16*)&v[j];
        __nv_bfloat16 o[8];
        #pragma unroll
        for (int k = 0; k < 8; k++)
            o[k] = __float2bfloat16(__bfloat162float(e[k]) * rz[ch * 8 + k]);
        *(uint4*)ptr[j] = *(uint4*)o;
    }
}

// ---------------------------------------------------------------------------
// Kernel: attn = E @ V' — optimal pairing: groups sum to exactly 32 k64 iters.
// g=0: {qt=15}; g=1..7: {15-g, g-1}; g=8: {qt=7}. 288 CTAs.
// ---------------------------------------------------------------------------
__device__ __forceinline__ void attnv_tile(
    int b, int qt, int n0, float* __restrict__ out)
{
    const int m0 = qt * 128;
    const int KT = 2 * (qt + 1);

    float acc[4][4][4] = {};
    gemm_loop(g_SP + ((size_t)b * NT + m0) * NT, NT,
              g_vT + ((size_t)b * NK + n0) * NT, NT,
              KT, acc);

    const int tid = threadIdx.x, wid = tid >> 5, lane = tid & 31;
    const int gid = lane >> 2, tig = lane & 3;
    const int wm = (wid & 1) * 64, wn = (wid >> 1) * 32;

    #pragma unroll
    for (int mt = 0; mt < 4; mt++) {
        #pragma unroll
        for (int nt = 0; nt < 4; nt++) {
            int q = m0 + wm + mt * 16 + gid;
            int n = n0 + wn + nt * 8 + 2 * tig;
            float2 v0 = { acc[mt][nt][0], acc[mt][nt][1] };
            float2 v1 = { acc[mt][nt][2], acc[mt][nt][3] };
            *(float2*)(out + ((size_t)b * NT + q) * 1024 + 512 + n) = v0;
            *(float2*)(out + ((size_t)b * NT + q + 8) * 1024 + 512 + n) = v1;
        }
    }
}

__global__ void __launch_bounds__(256, 2) attnv_kernel(float* __restrict__ out)
{
    const int g   = blockIdx.x >> 5;    // 0..8
    const int sub = blockIdx.x & 31;
    const int b   = sub >> 2;
    const int n0  = (sub & 3) * 128;

    if (g == 0) {
        attnv_tile(b, 15, n0, out);
    } else if (g <= 7) {
        attnv_tile(b, 15 - g, n0, out);  // big tile first
        __syncthreads();                 // smem reuse barrier between tiles
        attnv_tile(b, g - 1, n0, out);
    } else {
        attnv_tile(b, 7, n0, out);
    }
}

// ---------------------------------------------------------------------------
extern "C" void kernel_launch(void* const* d_in, const int* in_sizes, int n_in,
                              void* d_out, int out_size)
{
    const float* x  = (const float*)d_in[0];
    const float* Wq = (const float*)d_in[1];
    const float* bq = (const float*)d_in[2];
    const float* Wk = (const float*)d_in[3];
    const float* bk = (const float*)d_in[4];
    const float* Wv = (const float*)d_in[5];
    const float* bv = (const float*)d_in[6];
    float* out = (float*)d_out;

    // One-time stream/event resources (created outside capture on the first
    // correctness call; reused by the graph-capture call).
    static cudaStream_t s2 = nullptr;
    static cudaEvent_t evFork = nullptr, evJoin = nullptr;
    if (s2 == nullptr) {
        cudaStreamCreateWithFlags(&s2, cudaStreamNonBlocking);
        cudaEventCreateWithFlags(&evFork, cudaEventDisableTiming);
        cudaEventCreateWithFlags(&evJoin, cudaEventDisableTiming);
    }

    const int dsmem = NSTAGE * STAGE_B;  // 98304 B
    cudaFuncSetAttribute(qk_kernel,     cudaFuncAttributeMaxDynamicSharedMemorySize, dsmem);
    cudaFuncSetAttribute(v_kernel,      cudaFuncAttributeMaxDynamicSharedMemorySize, dsmem);
    cudaFuncSetAttribute(scores_kernel, cudaFuncAttributeMaxDynamicSharedMemorySize, dsmem);
    cudaFuncSetAttribute(attnv_kernel,  cudaFuncAttributeMaxDynamicSharedMemorySize, dsmem);

    conv_all<<<dim3(2304), 256>>>(x, out, Wq, Wk, Wv);

    // fork: V branch runs concurrently with qk + scores
    cudaEventRecord(evFork, 0);
    cudaStreamWaitEvent(s2, evFork, 0);
    v_kernel<<<dim3(4, 128), 256, dsmem, s2>>>(bv);
    cudaEventRecord(evJoin, s2);

    qk_kernel<<<dim3(4, 128, 2), 256, dsmem>>>(bq, bk);
    scores_kernel<<<dim3(136, 8), 256, dsmem>>>();

    // join: vscale needs both Z (scores) and g_vT (v_kernel)
    cudaStreamWaitEvent(0, evJoin, 0);
    vscale_kernel<<<dim3(32, 8, 4), 256>>>();
    attnv_kernel<<<dim3(288), 256, dsmem>>>(out);
}